// round 17
// baseline (speedup 1.0000x reference)
#include <cuda_runtime.h>
#include <cuda_fp16.h>
#include <cstdint>

#define NN   100000
#define EE   1600000
#define DHD  64
#define DINF 128

#define SCAN_T 256
#define SCAN_B ((NN + SCAN_T - 1) / SCAN_T)   // 391

// Scratch (static device globals — no allocation allowed)
__device__ int    g_cnt[NN];
__device__ int    g_offs[NN + 1];
__device__ int    g_part[SCAN_B];
__device__ int    g_rank[EE];
__device__ int    g_csr[EE];
__device__ float  g_dinv[NN];
__device__ __half g_h[NN * DHD];    // pre-scaled fp16 h' = (X@W)*dinv[row]
__device__ float  g_z[NN * DHD];    // inter-layer activation (fp32)
// Pre-split tf32 B-fragment tables: per (kstep, ntile, lane) -> (bh0,bh1,bl0,bl1)
__device__ float4 g_w1f[(DINF / 8) * 8 * 32];   // 4096 float4 = 64 KB
__device__ float4 g_w2f[(DHD  / 8) * 8 * 32];   // 2048 float4 = 32 KB

// Side stream + events for overlapping the CSR build with prep+GEMM1.
static cudaStream_t g_s2 = 0;
static cudaEvent_t  g_evFork = 0, g_evDinv = 0, g_evJoin = 0;
static bool g_overlap_ok = false;
static struct SideInit {
    SideInit() {
        g_overlap_ok =
            (cudaStreamCreateWithFlags(&g_s2, cudaStreamNonBlocking) == cudaSuccess) &&
            (cudaEventCreateWithFlags(&g_evFork, cudaEventDisableTiming) == cudaSuccess) &&
            (cudaEventCreateWithFlags(&g_evDinv, cudaEventDisableTiming) == cudaSuccess) &&
            (cudaEventCreateWithFlags(&g_evJoin, cudaEventDisableTiming) == cudaSuccess);
    }
} g_side_init;

// ---------------------------------------------------------------------------
__device__ __forceinline__ uint32_t f2tf32(float x) {
    uint32_t r;
    asm("cvt.rna.tf32.f32 %0, %1;" : "=r"(r) : "f"(x));
    return r;
}

__device__ __forceinline__ void mma8(float4& d, const uint32_t* a, uint32_t b0, uint32_t b1) {
    asm("mma.sync.aligned.m16n8k8.row.col.f32.tf32.tf32.f32 "
        "{%0,%1,%2,%3}, {%4,%5,%6,%7}, {%8,%9}, {%0,%1,%2,%3};"
        : "+f"(d.x), "+f"(d.y), "+f"(d.z), "+f"(d.w)
        : "r"(a[0]), "r"(a[1]), "r"(a[2]), "r"(a[3]), "r"(b0), "r"(b1));
}

// ---------------------------------------------------------------------------
// CSR build
// hist also records each edge's rank within its dst bucket (atomic's old value)
__global__ void k_hist(const int* __restrict__ dst, int* __restrict__ cnt,
                       int* __restrict__ rank, int e) {
    int i = blockIdx.x * blockDim.x + threadIdx.x;
    if (i < e) rank[i] = atomicAdd(&cnt[dst[i]], 1);
}

// pass 1 of scan + dinv (deg = cnt + 1 self-loop)
__global__ void k_scan_reduce(const int* __restrict__ cnt, int* __restrict__ part,
                              float* __restrict__ dinv, int n) {
    __shared__ int sh[SCAN_T];
    int i = blockIdx.x * SCAN_T + threadIdx.x;
    int v = (i < n) ? cnt[i] : 0;
    if (i < n) dinv[i] = rsqrtf((float)(v + 1));
    sh[threadIdx.x] = v;
    __syncthreads();
    for (int s = 1; s < SCAN_T; s <<= 1) {
        int add = (threadIdx.x >= s) ? sh[threadIdx.x - s] : 0;
        __syncthreads();
        sh[threadIdx.x] += add;
        __syncthreads();
    }
    if (threadIdx.x == SCAN_T - 1) part[blockIdx.x] = sh[SCAN_T - 1];
}

// pass 2 (fused top scan): each block reduces part[0..bid) itself, then local scan.
__global__ void k_scan_write(const int* __restrict__ cnt, const int* __restrict__ part,
                             int* __restrict__ offs, int n) {
    __shared__ int sh[SCAN_T];
    __shared__ int wsum[SCAN_T / 32];

    // block-exclusive base = sum of part[j], j < blockIdx.x
    int psum = 0;
    for (int j = threadIdx.x; j < blockIdx.x; j += SCAN_T) psum += part[j];
#pragma unroll
    for (int o = 16; o > 0; o >>= 1) psum += __shfl_down_sync(0xffffffffu, psum, o);
    if ((threadIdx.x & 31) == 0) wsum[threadIdx.x >> 5] = psum;
    __syncthreads();
    int base = 0;
#pragma unroll
    for (int w = 0; w < SCAN_T / 32; ++w) base += wsum[w];

    int i = blockIdx.x * SCAN_T + threadIdx.x;
    int v = (i < n) ? cnt[i] : 0;
    sh[threadIdx.x] = v;
    __syncthreads();
    for (int s = 1; s < SCAN_T; s <<= 1) {
        int add = (threadIdx.x >= s) ? sh[threadIdx.x - s] : 0;
        __syncthreads();
        sh[threadIdx.x] += add;
        __syncthreads();
    }
    if (i < n) {
        int incl = sh[threadIdx.x];
        int off = base + incl - v;   // exclusive
        offs[i] = off;
        if (i == n - 1) offs[n] = off + v;
    }
}

// atomic-free fill using precomputed ranks
__global__ void k_fill(const int* __restrict__ src, const int* __restrict__ dst,
                       const int* __restrict__ rank, const int* __restrict__ offs,
                       int* __restrict__ csr, int e) {
    int i = blockIdx.x * blockDim.x + threadIdx.x;
    if (i < e) {
        int pos = __ldg(offs + dst[i]) + rank[i];
        csr[pos] = src[i];
    }
}

// ---------------------------------------------------------------------------
// Prepare tf32 hi/lo fragment tables for W1 (K=128) and W2 (K=64).
__global__ void k_prep_w(const float* __restrict__ W1, const float* __restrict__ W2,
                         float4* __restrict__ F1, float4* __restrict__ F2) {
    int i = blockIdx.x * blockDim.x + threadIdx.x;
    const float* W;
    float4* F;
    int idx;
    if (i < (DINF / 8) * 8 * 32) { W = W1; F = F1; idx = i; }
    else if (i < (DINF / 8) * 8 * 32 + (DHD / 8) * 8 * 32) {
        W = W2; F = F2; idx = i - (DINF / 8) * 8 * 32;
    } else return;

    int lane = idx & 31;
    int nt   = (idx >> 5) & 7;
    int ks   = idx >> 8;
    int t = lane & 3, g = lane >> 2;

    float w0 = W[(ks * 8 + t)     * 64 + nt * 8 + g];
    float w1 = W[(ks * 8 + t + 4) * 64 + nt * 8 + g];
    uint32_t bh0 = f2tf32(w0);
    uint32_t bh1 = f2tf32(w1);
    uint32_t bl0 = f2tf32(w0 - __uint_as_float(bh0));
    uint32_t bl1 = f2tf32(w1 - __uint_as_float(bh1));
    F[idx] = make_float4(__uint_as_float(bh0), __uint_as_float(bh1),
                         __uint_as_float(bl0), __uint_as_float(bl1));
}

// ---------------------------------------------------------------------------
// Tensor-core GEMM (3xTF32) with dinv-scaled fp16 epilogue:
//   H'[row,:] = fp16( (X[row,:] @ W) * dinv[row] )
template <int K>
__global__ void __launch_bounds__(256) k_gemm_tc(
        const float* __restrict__ X, const float4* __restrict__ F,
        const float* __restrict__ dinv,
        __half* __restrict__ H, int n) {
    const int lane = threadIdx.x & 31;
    const int wid  = threadIdx.x >> 5;
    const int t = lane & 3, g = lane >> 2;

    const int row0 = blockIdx.x * 128 + wid * 16;
    int rlo = row0 + g;
    int rhi = row0 + 8 + g;
    int rloC = rlo < n ? rlo : n - 1;
    int rhiC = rhi < n ? rhi : n - 1;
    const float* Xlo = X + (size_t)rloC * K;
    const float* Xhi = X + (size_t)rhiC * K;

    float4 d[8];
#pragma unroll
    for (int nt = 0; nt < 8; ++nt) d[nt] = make_float4(0.f, 0.f, 0.f, 0.f);

#pragma unroll
    for (int ks = 0; ks < K / 8; ++ks) {
        int k0 = ks * 8;
        float af0 = __ldg(Xlo + k0 + t);
        float af1 = __ldg(Xhi + k0 + t);
        float af2 = __ldg(Xlo + k0 + t + 4);
        float af3 = __ldg(Xhi + k0 + t + 4);

        uint32_t ah[4], al[4];
        ah[0] = f2tf32(af0); al[0] = f2tf32(af0 - __uint_as_float(ah[0]));
        ah[1] = f2tf32(af1); al[1] = f2tf32(af1 - __uint_as_float(ah[1]));
        ah[2] = f2tf32(af2); al[2] = f2tf32(af2 - __uint_as_float(ah[2]));
        ah[3] = f2tf32(af3); al[3] = f2tf32(af3 - __uint_as_float(ah[3]));

#pragma unroll
        for (int nt = 0; nt < 8; ++nt) {
            float4 fr = __ldg(F + (size_t)(ks * 8 + nt) * 32 + lane);
            uint32_t bh0 = __float_as_uint(fr.x);
            uint32_t bh1 = __float_as_uint(fr.y);
            uint32_t bl0 = __float_as_uint(fr.z);
            uint32_t bl1 = __float_as_uint(fr.w);
            mma8(d[nt], ah, bh0, bh1);   // hi*hi
            mma8(d[nt], ah, bl0, bl1);   // hi*lo
            mma8(d[nt], al, bh0, bh1);   // lo*hi
        }
    }

    bool okLo = (row0 + g) < n;
    bool okHi = (row0 + 8 + g) < n;
    float sLo = okLo ? __ldg(dinv + row0 + g) : 0.f;
    float sHi = okHi ? __ldg(dinv + row0 + 8 + g) : 0.f;
    __half* HLo = H + (size_t)(row0 + g) * 64;
    __half* HHi = H + (size_t)(row0 + 8 + g) * 64;
#pragma unroll
    for (int nt = 0; nt < 8; ++nt) {
        int c = nt * 8 + 2 * t;
        if (okLo)
            *(__half2*)(HLo + c) = __float22half2_rn(make_float2(d[nt].x * sLo, d[nt].y * sLo));
        if (okHi)
            *(__half2*)(HHi + c) = __float22half2_rn(make_float2(d[nt].z * sHi, d[nt].w * sHi));
    }
}

// ---------------------------------------------------------------------------
// Warp-per-2-nodes gather over pre-scaled fp16 h', fp32 accum, 4-way MLP:
//   out[d] = prelu( dinv[d] * ( sum_{s in N(d)} h'[s] + h'[d] ) + b )
// All inner-loop conditions are warp-uniform (no divergence, pure predication).
__global__ void __launch_bounds__(256) k_gather(
        const __half* __restrict__ h, const int* __restrict__ csr,
        const int* __restrict__ offs, const float* __restrict__ dinv,
        const float* __restrict__ b, const float* __restrict__ alpha,
        float* __restrict__ out, int n) {
    int warp = blockIdx.x * 8 + (threadIdx.x >> 5);
    int lane = threadIdx.x & 31;
    int n0 = warp * 2;
    int n1 = n0 + 1;
    if (n0 >= n) return;
    bool ok1 = n1 < n;

    int beg0 = offs[n0], end0 = offs[n0 + 1];
    int beg1 = ok1 ? offs[n1] : 0;
    int end1 = ok1 ? offs[n1 + 1] : 0;
    float dd0 = dinv[n0];
    float dd1 = ok1 ? dinv[n1] : 0.f;

    // self-loop terms (h' already carries dinv[node])
    float2 a00 = __half22float2(((const __half2*)h)[(size_t)n0 * 32 + lane]);
    float2 a01 = make_float2(0.f, 0.f);
    float2 a10 = ok1 ? __half22float2(((const __half2*)h)[(size_t)n1 * 32 + lane])
                     : make_float2(0.f, 0.f);
    float2 a11 = make_float2(0.f, 0.f);

    int c0 = end0 - beg0;
    int c1 = end1 - beg1;
    int cmax = c0 > c1 ? c0 : c1;

    for (int base = 0; base < cmax; base += 32) {
        int r0 = c0 - base;
        int r1 = c1 - base;
        int sid0 = (lane < r0) ? __ldg(csr + beg0 + base + lane) : 0;
        int sid1 = (lane < r1) ? __ldg(csr + beg1 + base + lane) : 0;
        int m0 = r0 < 0 ? 0 : (r0 < 32 ? r0 : 32);
        int m1 = r1 < 0 ? 0 : (r1 < 32 ? r1 : 32);
        int mm = m0 > m1 ? m0 : m1;

        for (int k = 0; k < mm; k += 2) {
            int s00 = __shfl_sync(0xffffffffu, sid0, k);
            int s01 = __shfl_sync(0xffffffffu, sid0, k + 1);
            int s10 = __shfl_sync(0xffffffffu, sid1, k);
            int s11 = __shfl_sync(0xffffffffu, sid1, k + 1);
            if (k < m0) {
                float2 v = __half22float2(__ldg((const __half2*)h + (size_t)s00 * 32 + lane));
                a00.x += v.x; a00.y += v.y;
            }
            if (k + 1 < m0) {
                float2 v = __half22float2(__ldg((const __half2*)h + (size_t)s01 * 32 + lane));
                a01.x += v.x; a01.y += v.y;
            }
            if (k < m1) {
                float2 v = __half22float2(__ldg((const __half2*)h + (size_t)s10 * 32 + lane));
                a10.x += v.x; a10.y += v.y;
            }
            if (k + 1 < m1) {
                float2 v = __half22float2(__ldg((const __half2*)h + (size_t)s11 * 32 + lane));
                a11.x += v.x; a11.y += v.y;
            }
        }
    }

    float2 bb = ((const float2*)b)[lane];
    float2 al = ((const float2*)alpha)[lane];

    a00.x += a01.x; a00.y += a01.y;
    a00.x = a00.x * dd0 + bb.x;
    a00.y = a00.y * dd0 + bb.y;
    a00.x = (a00.x >= 0.f) ? a00.x : al.x * a00.x;
    a00.y = (a00.y >= 0.f) ? a00.y : al.y * a00.y;
    ((float2*)out)[(size_t)n0 * 32 + lane] = a00;

    if (ok1) {
        a10.x += a11.x; a10.y += a11.y;
        a10.x = a10.x * dd1 + bb.x;
        a10.y = a10.y * dd1 + bb.y;
        a10.x = (a10.x >= 0.f) ? a10.x : al.x * a10.x;
        a10.y = (a10.y >= 0.f) ? a10.y : al.y * a10.y;
        ((float2*)out)[(size_t)n1 * 32 + lane] = a10;
    }
}

// ---------------------------------------------------------------------------
extern "C" void kernel_launch(void* const* d_in, const int* in_sizes, int n_in,
                              void* d_out, int out_size) {
    const float* x     = (const float*)d_in[0];
    const int*   ei    = (const int*)d_in[1];
    const float* W1    = (const float*)d_in[2];
    const float* b1    = (const float*)d_in[3];
    const float* W2    = (const float*)d_in[4];
    const float* b2    = (const float*)d_in[5];
    const float* alpha = (const float*)d_in[6];
    float*       out   = (float*)d_out;

    int n = in_sizes[0] / DINF;   // 100000
    int e = in_sizes[1] / 2;      // 1600000
    const int* src = ei;
    const int* dst = ei + e;

    void* p;
    cudaGetSymbolAddress(&p, g_cnt);  int*    cnt  = (int*)p;
    cudaGetSymbolAddress(&p, g_offs); int*    offs = (int*)p;
    cudaGetSymbolAddress(&p, g_part); int*    part = (int*)p;
    cudaGetSymbolAddress(&p, g_rank); int*    rank = (int*)p;
    cudaGetSymbolAddress(&p, g_csr);  int*    csr  = (int*)p;
    cudaGetSymbolAddress(&p, g_dinv); float*  dinv = (float*)p;
    cudaGetSymbolAddress(&p, g_h);    __half* h    = (__half*)p;
    cudaGetSymbolAddress(&p, g_z);    float*  z    = (float*)p;
    cudaGetSymbolAddress(&p, g_w1f);  float4* f1   = (float4*)p;
    cudaGetSymbolAddress(&p, g_w2f);  float4* f2   = (float4*)p;

    const int T = 256;
    cudaStream_t sb = g_overlap_ok ? g_s2 : (cudaStream_t)0;

    // ---- fork: CSR build on side stream; prep + GEMM1 on main ----
    if (g_overlap_ok) {
        cudaEventRecord(g_evFork, 0);
        cudaStreamWaitEvent(sb, g_evFork, 0);
    }

    cudaMemsetAsync(cnt, 0, (size_t)n * sizeof(int), sb);
    k_hist<<<(e + T - 1) / T, T, 0, sb>>>(dst, cnt, rank, e);
    k_scan_reduce<<<SCAN_B, SCAN_T, 0, sb>>>(cnt, part, dinv, n);
    if (g_overlap_ok) cudaEventRecord(g_evDinv, sb);
    k_scan_write<<<SCAN_B, SCAN_T, 0, sb>>>(cnt, part, offs, n);
    k_fill<<<(e + T - 1) / T, T, 0, sb>>>(src, dst, rank, offs, csr, e);

    k_prep_w<<<24, 256>>>(W1, W2, f1, f2);
    if (g_overlap_ok) cudaStreamWaitEvent(0, g_evDinv, 0);
    k_gemm_tc<DINF><<<(n + 127) / 128, T>>>(x, f1, dinv, h, n);

    if (g_overlap_ok) {
        cudaEventRecord(g_evJoin, sb);
        cudaStreamWaitEvent(0, g_evJoin, 0);
    }

    // ---- layer 1 aggregate + layer 2 ----
    int gblocks = (n + 15) / 16;   // 8 warps/block, 2 nodes/warp
    k_gather<<<gblocks, T>>>(h, csr, offs, dinv, b1, alpha, z, n);
    k_gemm_tc<DHD><<<(n + 127) / 128, T>>>(z, f2, dinv, h, n);
    k_gather<<<gblocks, T>>>(h, csr, offs, dinv, b2, alpha, out, n);
}